// round 1
// baseline (speedup 1.0000x reference)
#include <cuda_runtime.h>
#include <math.h>

#define BATCH   32
#define NSRC    4
#define TLEN    64000
#define T4      (TLEN / 4)      // 16000 float4 per stream per batch
#define CHUNKS  32              // blocks per batch
#define PER_BLK (T4 / CHUNKS)   // 500 float4 per block per stream
#define NSTAT   20
#define NK      16
#define THREADS 256

// Per-block partial sums: [batch][chunk][stat]. Fully overwritten every call.
__device__ float g_partials[BATCH * CHUNKS * NSTAT];

// stat layout:
//  0..9  : Gram upper triangle (0,0)(0,1)(0,2)(0,3)(1,1)(1,2)(1,3)(2,2)(2,3)(3,3)
// 10..13 : P1[s] = sum e_s * m1
// 14..17 : P2[s] = sum e_s * m2
// 18     : ||m1||^2
// 19     : ||m2||^2

__global__ __launch_bounds__(THREADS)
void stats_kernel(const float* __restrict__ est,
                  const float* __restrict__ m1,
                  const float* __restrict__ m2)
{
    const int blk   = blockIdx.x;          // b * CHUNKS + chunk
    const int b     = blk / CHUNKS;
    const int chunk = blk % CHUNKS;
    const int start = chunk * PER_BLK;
    const int end   = start + PER_BLK;

    const float4* e0 = (const float4*)(est + (size_t)b * NSRC * TLEN + 0 * (size_t)TLEN);
    const float4* e1 = (const float4*)(est + (size_t)b * NSRC * TLEN + 1 * (size_t)TLEN);
    const float4* e2 = (const float4*)(est + (size_t)b * NSRC * TLEN + 2 * (size_t)TLEN);
    const float4* e3 = (const float4*)(est + (size_t)b * NSRC * TLEN + 3 * (size_t)TLEN);
    const float4* p1 = (const float4*)(m1 + (size_t)b * TLEN);
    const float4* p2 = (const float4*)(m2 + (size_t)b * TLEN);

    float acc[NSTAT];
#pragma unroll
    for (int i = 0; i < NSTAT; i++) acc[i] = 0.0f;

    for (int i = start + threadIdx.x; i < end; i += THREADS) {
        float4 a0 = e0[i], a1 = e1[i], a2 = e2[i], a3 = e3[i];
        float4 v1 = p1[i], v2 = p2[i];

#define LANE(C) do {                                                       \
        float x0 = a0.C, x1 = a1.C, x2 = a2.C, x3 = a3.C;                  \
        float y1 = v1.C, y2 = v2.C;                                        \
        acc[0]  = fmaf(x0, x0, acc[0]);                                    \
        acc[1]  = fmaf(x0, x1, acc[1]);                                    \
        acc[2]  = fmaf(x0, x2, acc[2]);                                    \
        acc[3]  = fmaf(x0, x3, acc[3]);                                    \
        acc[4]  = fmaf(x1, x1, acc[4]);                                    \
        acc[5]  = fmaf(x1, x2, acc[5]);                                    \
        acc[6]  = fmaf(x1, x3, acc[6]);                                    \
        acc[7]  = fmaf(x2, x2, acc[7]);                                    \
        acc[8]  = fmaf(x2, x3, acc[8]);                                    \
        acc[9]  = fmaf(x3, x3, acc[9]);                                    \
        acc[10] = fmaf(x0, y1, acc[10]);                                   \
        acc[11] = fmaf(x1, y1, acc[11]);                                   \
        acc[12] = fmaf(x2, y1, acc[12]);                                   \
        acc[13] = fmaf(x3, y1, acc[13]);                                   \
        acc[14] = fmaf(x0, y2, acc[14]);                                   \
        acc[15] = fmaf(x1, y2, acc[15]);                                   \
        acc[16] = fmaf(x2, y2, acc[16]);                                   \
        acc[17] = fmaf(x3, y2, acc[17]);                                   \
        acc[18] = fmaf(y1, y1, acc[18]);                                   \
        acc[19] = fmaf(y2, y2, acc[19]);                                   \
    } while (0)

        LANE(x); LANE(y); LANE(z); LANE(w);
#undef LANE
    }

    // warp reduce each stat
#pragma unroll
    for (int st = 0; st < NSTAT; st++) {
        float v = acc[st];
        v += __shfl_down_sync(0xffffffffu, v, 16);
        v += __shfl_down_sync(0xffffffffu, v, 8);
        v += __shfl_down_sync(0xffffffffu, v, 4);
        v += __shfl_down_sync(0xffffffffu, v, 2);
        v += __shfl_down_sync(0xffffffffu, v, 1);
        acc[st] = v;
    }

    __shared__ float sred[THREADS / 32][NSTAT];
    const int warp = threadIdx.x >> 5;
    const int lane = threadIdx.x & 31;
    if (lane == 0) {
#pragma unroll
        for (int st = 0; st < NSTAT; st++) sred[warp][st] = acc[st];
    }
    __syncthreads();

    if (threadIdx.x < NSTAT) {
        float s = 0.0f;
#pragma unroll
        for (int w = 0; w < THREADS / 32; w++) s += sred[w][threadIdx.x];
        g_partials[blk * NSTAT + threadIdx.x] = s;
    }
}

__global__ __launch_bounds__(512)
void loss_kernel(float* __restrict__ out, int out_size)
{
    __shared__ double sstats[BATCH][NSTAT];   // 5 KB
    __shared__ double klb[NK][BATCH];         // 4 KB

    const int tid = threadIdx.x;

    // Phase 1: deterministic reduce of per-chunk partials (double)
    for (int idx = tid; idx < BATCH * NSTAT; idx += 512) {
        int b  = idx / NSTAT;
        int st = idx % NSTAT;
        double s = 0.0;
#pragma unroll
        for (int c = 0; c < CHUNKS; c++)
            s += (double)g_partials[(b * CHUNKS + c) * NSTAT + st];
        sstats[b][st] = s;
    }
    __syncthreads();

    // Phase 2: loss for every (k, b) pair. 16*32 = 512 threads exactly.
    const int k = tid >> 5;
    const int b = tid & 31;

    double m[NSRC], mc[NSRC];
#pragma unroll
    for (int s = 0; s < NSRC; s++) {
        m[s]  = (double)((k >> (3 - s)) & 1);   // itertools.product: last varies fastest
        mc[s] = 1.0 - m[s];
    }

    const int gi[4][4] = {{0,1,2,3},{1,4,5,6},{2,5,7,8},{3,6,8,9}};

    double q0 = 0.0, q1 = 0.0, c0 = 0.0, c1 = 0.0;
#pragma unroll
    for (int s = 0; s < NSRC; s++) {
#pragma unroll
        for (int s2 = 0; s2 < NSRC; s2++) {
            double g = sstats[b][gi[s][s2]];
            q0 += m[s]  * m[s2]  * g;
            q1 += mc[s] * mc[s2] * g;
        }
        c0 += m[s]  * sstats[b][10 + s];
        c1 += mc[s] * sstats[b][14 + s];
    }
    const double M1 = sstats[b][18];
    const double M2 = sstats[b][19];

    const double a0 = q0 - 2.0 * c0 + M1;   // ||mix0 - m1||^2
    const double a1 = q1 - 2.0 * c1 + M2;   // ||mix1 - m2||^2

    const double loss =
        10.0 * (log10(a0 + 30.0 * q0) - log10(q0)) +
        10.0 * (log10(a1 + 30.0 * q1) - log10(q1));

    klb[k][b] = loss;
    __syncthreads();

    // Phase 3: tree-reduce over b per k
    if (b < 16) klb[k][b] += klb[k][b + 16]; __syncthreads();
    if (b < 8)  klb[k][b] += klb[k][b + 8];  __syncthreads();
    if (b < 4)  klb[k][b] += klb[k][b + 4];  __syncthreads();
    if (b < 2)  klb[k][b] += klb[k][b + 2];  __syncthreads();
    if (b < 1)  klb[k][b] += klb[k][b + 1];  __syncthreads();

    if (tid == 0) {
        double best = klb[0][0];
        int bi = 0;
#pragma unroll
        for (int kk = 1; kk < NK; kk++) {
            double v = klb[kk][0];
            if (v < best) { best = v; bi = kk; }   // first occurrence wins, matches jnp.argmin
        }
        out[0] = (float)bi;
        if (out_size > 1) out[1] = (float)best;
    }
}

extern "C" void kernel_launch(void* const* d_in, const int* in_sizes, int n_in,
                              void* d_out, int out_size)
{
    const float* est = (const float*)d_in[0];   // [32, 4, 64000]
    const float* m1  = (const float*)d_in[1];   // [32, 64000]
    const float* m2  = (const float*)d_in[2];   // [32, 64000]

    stats_kernel<<<BATCH * CHUNKS, THREADS>>>(est, m1, m2);
    loss_kernel<<<1, 512>>>((float*)d_out, out_size);
}

// round 2
// speedup vs baseline: 3.7586x; 3.7586x over previous
#include <cuda_runtime.h>
#include <math.h>

#define BATCH   32
#define NSRC    4
#define TLEN    64000
#define T4      (TLEN / 4)      // 16000 float4 per stream per batch
#define CHUNKS  32              // blocks per batch
#define PER_BLK (T4 / CHUNKS)   // 500 float4 per block per stream
#define NSTAT   20
#define NK      16
#define THREADS 256

// Per-block partial sums: [batch][chunk][stat]. Fully overwritten every call.
__device__ float g_partials[BATCH * CHUNKS * NSTAT];

// stat layout:
//  0..9  : Gram upper triangle (0,0)(0,1)(0,2)(0,3)(1,1)(1,2)(1,3)(2,2)(2,3)(3,3)
// 10..13 : P1[s] = sum e_s * m1
// 14..17 : P2[s] = sum e_s * m2
// 18     : ||m1||^2
// 19     : ||m2||^2

__global__ __launch_bounds__(THREADS)
void stats_kernel(const float* __restrict__ est,
                  const float* __restrict__ m1,
                  const float* __restrict__ m2)
{
    const int blk   = blockIdx.x;          // b * CHUNKS + chunk
    const int b     = blk / CHUNKS;
    const int chunk = blk % CHUNKS;
    const int start = chunk * PER_BLK;
    const int end   = start + PER_BLK;

    const float4* e0 = (const float4*)(est + (size_t)b * NSRC * TLEN + 0 * (size_t)TLEN);
    const float4* e1 = (const float4*)(est + (size_t)b * NSRC * TLEN + 1 * (size_t)TLEN);
    const float4* e2 = (const float4*)(est + (size_t)b * NSRC * TLEN + 2 * (size_t)TLEN);
    const float4* e3 = (const float4*)(est + (size_t)b * NSRC * TLEN + 3 * (size_t)TLEN);
    const float4* p1 = (const float4*)(m1 + (size_t)b * TLEN);
    const float4* p2 = (const float4*)(m2 + (size_t)b * TLEN);

    float acc[NSTAT];
#pragma unroll
    for (int i = 0; i < NSTAT; i++) acc[i] = 0.0f;

    for (int i = start + threadIdx.x; i < end; i += THREADS) {
        float4 a0 = e0[i], a1 = e1[i], a2 = e2[i], a3 = e3[i];
        float4 v1 = p1[i], v2 = p2[i];

#define LANE(C) do {                                                       \
        float x0 = a0.C, x1 = a1.C, x2 = a2.C, x3 = a3.C;                  \
        float y1 = v1.C, y2 = v2.C;                                        \
        acc[0]  = fmaf(x0, x0, acc[0]);                                    \
        acc[1]  = fmaf(x0, x1, acc[1]);                                    \
        acc[2]  = fmaf(x0, x2, acc[2]);                                    \
        acc[3]  = fmaf(x0, x3, acc[3]);                                    \
        acc[4]  = fmaf(x1, x1, acc[4]);                                    \
        acc[5]  = fmaf(x1, x2, acc[5]);                                    \
        acc[6]  = fmaf(x1, x3, acc[6]);                                    \
        acc[7]  = fmaf(x2, x2, acc[7]);                                    \
        acc[8]  = fmaf(x2, x3, acc[8]);                                    \
        acc[9]  = fmaf(x3, x3, acc[9]);                                    \
        acc[10] = fmaf(x0, y1, acc[10]);                                   \
        acc[11] = fmaf(x1, y1, acc[11]);                                   \
        acc[12] = fmaf(x2, y1, acc[12]);                                   \
        acc[13] = fmaf(x3, y1, acc[13]);                                   \
        acc[14] = fmaf(x0, y2, acc[14]);                                   \
        acc[15] = fmaf(x1, y2, acc[15]);                                   \
        acc[16] = fmaf(x2, y2, acc[16]);                                   \
        acc[17] = fmaf(x3, y2, acc[17]);                                   \
        acc[18] = fmaf(y1, y1, acc[18]);                                   \
        acc[19] = fmaf(y2, y2, acc[19]);                                   \
    } while (0)

        LANE(x); LANE(y); LANE(z); LANE(w);
#undef LANE
    }

    // warp reduce each stat
#pragma unroll
    for (int st = 0; st < NSTAT; st++) {
        float v = acc[st];
        v += __shfl_down_sync(0xffffffffu, v, 16);
        v += __shfl_down_sync(0xffffffffu, v, 8);
        v += __shfl_down_sync(0xffffffffu, v, 4);
        v += __shfl_down_sync(0xffffffffu, v, 2);
        v += __shfl_down_sync(0xffffffffu, v, 1);
        acc[st] = v;
    }

    __shared__ float sred[THREADS / 32][NSTAT];
    const int warp = threadIdx.x >> 5;
    const int lane = threadIdx.x & 31;
    if (lane == 0) {
#pragma unroll
        for (int st = 0; st < NSTAT; st++) sred[warp][st] = acc[st];
    }
    __syncthreads();

    if (threadIdx.x < NSTAT) {
        float s = 0.0f;
#pragma unroll
        for (int w = 0; w < THREADS / 32; w++) s += sred[w][threadIdx.x];
        g_partials[blk * NSTAT + threadIdx.x] = s;
    }
}

// Epilogue: ALL fp32 (FP64 pipe on one SM was 46us in R1). __log10f = MUFU.LG2.
__global__ __launch_bounds__(512)
void loss_kernel(float* __restrict__ out, int out_size)
{
    __shared__ float sstats[BATCH][NSTAT];   // 2.5 KB
    __shared__ float klb[NK][BATCH];         // 2 KB

    const int tid = threadIdx.x;

    // Phase 1: deterministic reduce of per-chunk partials.
    // 640 sums of 32 independent fp32 loads each; 512 threads, fixed order.
    for (int idx = tid; idx < BATCH * NSTAT; idx += 512) {
        int b  = idx / NSTAT;
        int st = idx % NSTAT;
        float s = 0.0f;
#pragma unroll
        for (int c = 0; c < CHUNKS; c++)
            s += g_partials[(b * CHUNKS + c) * NSTAT + st];
        sstats[b][st] = s;
    }
    __syncthreads();

    // Phase 2: loss for every (k, b) pair. 16*32 = 512 threads exactly.
    const int k = tid >> 5;
    const int b = tid & 31;

    float m[NSRC], mc[NSRC];
#pragma unroll
    for (int s = 0; s < NSRC; s++) {
        m[s]  = (float)((k >> (3 - s)) & 1);   // itertools.product: last varies fastest
        mc[s] = 1.0f - m[s];
    }

    const int gi[4][4] = {{0,1,2,3},{1,4,5,6},{2,5,7,8},{3,6,8,9}};

    float q0 = 0.0f, q1 = 0.0f, c0 = 0.0f, c1 = 0.0f;
#pragma unroll
    for (int s = 0; s < NSRC; s++) {
#pragma unroll
        for (int s2 = 0; s2 < NSRC; s2++) {
            float g = sstats[b][gi[s][s2]];
            q0 = fmaf(m[s]  * m[s2],  g, q0);
            q1 = fmaf(mc[s] * mc[s2], g, q1);
        }
        c0 = fmaf(m[s],  sstats[b][10 + s], c0);
        c1 = fmaf(mc[s], sstats[b][14 + s], c1);
    }
    const float M1 = sstats[b][18];
    const float M2 = sstats[b][19];

    const float a0 = q0 - 2.0f * c0 + M1;   // ||mix0 - m1||^2
    const float a1 = q1 - 2.0f * c1 + M2;   // ||mix1 - m2||^2

    const float loss =
        10.0f * (__log10f(fmaf(30.0f, q0, a0)) - __log10f(q0)) +
        10.0f * (__log10f(fmaf(30.0f, q1, a1)) - __log10f(q1));

    klb[k][b] = loss;
    __syncthreads();

    // Phase 3: tree-reduce over b per k (fixed order, deterministic)
    if (b < 16) klb[k][b] += klb[k][b + 16]; __syncthreads();
    if (b < 8)  klb[k][b] += klb[k][b + 8];  __syncthreads();
    if (b < 4)  klb[k][b] += klb[k][b + 4];  __syncthreads();
    if (b < 2)  klb[k][b] += klb[k][b + 2];  __syncthreads();
    if (b < 1)  klb[k][b] += klb[k][b + 1];  __syncthreads();

    if (tid == 0) {
        float best = klb[0][0];
        int bi = 0;
#pragma unroll
        for (int kk = 1; kk < NK; kk++) {
            float v = klb[kk][0];
            if (v < best) { best = v; bi = kk; }   // first occurrence wins, matches jnp.argmin
        }
        out[0] = (float)bi;
        if (out_size > 1) out[1] = best;
    }
}

extern "C" void kernel_launch(void* const* d_in, const int* in_sizes, int n_in,
                              void* d_out, int out_size)
{
    const float* est = (const float*)d_in[0];   // [32, 4, 64000]
    const float* m1  = (const float*)d_in[1];   // [32, 64000]
    const float* m2  = (const float*)d_in[2];   // [32, 64000]

    stats_kernel<<<BATCH * CHUNKS, THREADS>>>(est, m1, m2);
    loss_kernel<<<1, 512>>>((float*)d_out, out_size);
}